// round 7
// baseline (speedup 1.0000x reference)
#include <cuda_runtime.h>
#include <cstdint>

// LIF neuron Euler step (TemporalReceptiveField), pure elementwise, HBM-bound.
// R6: 256-bit vector memory ops (ld/st.global.cs.v8.b32 -> LDG.E.256/STG.E.256,
//     sm_100a+). One v8 chunk (8 floats) per thread per stream; exact cover.

#define DT           0.001f
#define TAU_SYN_INV  200.0f
#define V_TH         1.0f

static constexpr int N_ELEMS = 16 * 64 * 128 * 128;   // 16,777,216
static constexpr int N8      = N_ELEMS / 8;           // 2,097,152 v8 chunks
static constexpr int THREADS = 256;
static constexpr int BLOCKS  = N8 / THREADS;          // 8192, exact cover

__device__ __forceinline__ void ld8_cs(uint32_t r[8], const void* p) {
    asm volatile("ld.global.cs.v8.b32 {%0,%1,%2,%3,%4,%5,%6,%7}, [%8];"
                 : "=r"(r[0]), "=r"(r[1]), "=r"(r[2]), "=r"(r[3]),
                   "=r"(r[4]), "=r"(r[5]), "=r"(r[6]), "=r"(r[7])
                 : "l"(p));
}

__device__ __forceinline__ void st8_cs(void* p, const uint32_t r[8]) {
    asm volatile("st.global.cs.v8.b32 [%0], {%1,%2,%3,%4,%5,%6,%7,%8};"
                 :: "l"(p),
                    "r"(r[0]), "r"(r[1]), "r"(r[2]), "r"(r[3]),
                    "r"(r[4]), "r"(r[5]), "r"(r[6]), "r"(r[7])
                 : "memory");
}

__global__ __launch_bounds__(THREADS)
void lif_step_kernel(const float* __restrict__ x,
                     const float* __restrict__ v0,
                     const float* __restrict__ i0,
                     const float* __restrict__ ps,
                     float* __restrict__ z_out,
                     float* __restrict__ v_out,
                     float* __restrict__ i_out)
{
    const int i = blockIdx.x * THREADS + threadIdx.x;   // v8-chunk index, exact cover
    const long long e = (long long)i * 8;               // element offset

    // Front-batch the 3 x 256-bit loads (streaming: no reuse).
    uint32_t xv[8], vv[8], iv[8];
    ld8_cs(xv, x  + e);
    ld8_cs(vv, v0 + e);
    ld8_cs(iv, i0 + e);

    // channel = (element / (H*W)) % C -> H*W = 16384 elems = 2048 v8 chunks
    const int   c      = (i >> 11) & 63;
    const float dt_tau = DT * __ldg(ps + c);
    const float syn_k  = DT * TAU_SYN_INV;              // 0.2f, matching ref op order

    uint32_t zr[8], vr[8], ir[8];
    #pragma unroll
    for (int k = 0; k < 8; k++) {
        const float xf = __uint_as_float(xv[k]);
        const float vf = __uint_as_float(vv[k]);
        const float jf = __uint_as_float(iv[k]);

        const float vd = fmaf(dt_tau, jf - vf, vf);
        const float z  = (vd - V_TH > 0.0f) ? 1.0f : 0.0f;
        const float vn = (z > 0.0f) ? 0.0f : vd;
        const float in = (jf - syn_k * jf) + xf;

        zr[k] = __float_as_uint(z);
        vr[k] = __float_as_uint(vn);
        ir[k] = __float_as_uint(in);
    }

    st8_cs(z_out + e, zr);
    st8_cs(v_out + e, vr);
    st8_cs(i_out + e, ir);
}

extern "C" void kernel_launch(void* const* d_in, const int* in_sizes, int n_in,
                              void* d_out, int out_size)
{
    const float* x  = (const float*)d_in[0];
    const float* v0 = (const float*)d_in[1];
    const float* i0 = (const float*)d_in[2];
    const float* ps = (const float*)d_in[3];

    float* out   = (float*)d_out;
    float* z_out = out;
    float* v_out = out + N_ELEMS;
    float* i_out = out + 2 * N_ELEMS;

    lif_step_kernel<<<BLOCKS, THREADS>>>(x, v0, i0, ps, z_out, v_out, i_out);
}